// round 15
// baseline (speedup 1.0000x reference)
#include <cuda_runtime.h>
#include <cuda_fp16.h>

#define NN   100000
#define EE_MAX 1600000
#define ET_MAX (NN + EE_MAX)
#define FIN  165
#define HID  64

// ---------------- scratch (device globals; no allocation allowed) ------------
__device__ float4 g_h1f[NN * 8];        // layer-1 features fp16: 8 float4 = 32 half2 per row
__device__ float  g_s1[NN], g_d1[NN];
__device__ float4 g_p2[NN];             // packed (h2.x, h2.y, s2, d2)
__device__ int    g_deg[NN];
__device__ int    g_epos[EE_MAX];       // within-row position of each edge
__device__ int    g_rowptr[NN + 1];
__device__ int    g_esrc[ET_MAX];
__device__ int    g_edst[ET_MAX];       // dst per CSR slot (for ew precompute)
__device__ float  g_ew[ET_MAX];         // per-edge softmax numerator
__device__ int    g_bsum[128], g_boff[128];

// side stream + events for capture fork/join (host-side resources, module load)
struct HxStreams {
    cudaStream_t s2;
    cudaEvent_t evA, evB, evC;
    HxStreams() {
        cudaStreamCreateWithFlags(&s2, cudaStreamNonBlocking);
        cudaEventCreateWithFlags(&evA, cudaEventDisableTiming);
        cudaEventCreateWithFlags(&evB, cudaEventDisableTiming);
        cudaEventCreateWithFlags(&evC, cudaEventDisableTiming);
    }
};
static HxStreams g_hx;

// ------- GEMM1: h1 = x @ W1 (100000x165 @ 165x64), fused s1/d1 epilogue -----
__global__ void k_gemm1(const float* __restrict__ x, const float* __restrict__ W1,
                        const float* __restrict__ a1s, const float* __restrict__ a1d) {
    __shared__ float As[16][64];   // As[kk][row]
    __shared__ float Bs[16][64];   // Bs[kk][col]
    const int row0 = blockIdx.x * 64;
    const int tid  = threadIdx.x;        // 0..255
    const int tx   = tid & 15;           // col group (4 cols each)
    const int ty   = tid >> 4;           // row group (4 rows each)
    float acc[4][4] = {};

    for (int k0 = 0; k0 < FIN; k0 += 16) {
        #pragma unroll
        for (int i = 0; i < 4; i++) {
            int idx = tid * 4 + i;          // 0..1023
            int r  = idx >> 4;              // 0..63
            int kk = idx & 15;
            int gr = row0 + r, gk = k0 + kk;
            As[kk][r] = (gr < NN && gk < FIN) ? x[gr * FIN + gk] : 0.f;
        }
        #pragma unroll
        for (int i = 0; i < 4; i++) {
            int idx = tid * 4 + i;
            int kk = idx >> 6;              // 0..15
            int c  = idx & 63;
            int gk = k0 + kk;
            Bs[kk][c] = (gk < FIN) ? W1[gk * HID + c] : 0.f;
        }
        __syncthreads();
        #pragma unroll
        for (int kk = 0; kk < 16; kk++) {
            float a[4], b[4];
            #pragma unroll
            for (int i = 0; i < 4; i++) a[i] = As[kk][ty * 4 + i];
            #pragma unroll
            for (int i = 0; i < 4; i++) b[i] = Bs[kk][tx * 4 + i];
            #pragma unroll
            for (int i = 0; i < 4; i++)
                #pragma unroll
                for (int j = 0; j < 4; j++)
                    acc[i][j] += a[i] * b[j];
        }
        __syncthreads();
    }

    // store h1 as fp16 (cols tx*4 .. tx*4+3 -> half2 slots tx*2, tx*2+1 of the row)
    __half2* h1h = (__half2*)g_h1f;
    #pragma unroll
    for (int i = 0; i < 4; i++) {
        int gr = row0 + ty * 4 + i;
        if (gr < NN) {
            h1h[gr * 32 + tx * 2 + 0] = __floats2half2_rn(acc[i][0], acc[i][1]);
            h1h[gr * 32 + tx * 2 + 1] = __floats2half2_rn(acc[i][2], acc[i][3]);
        }
    }

    // fused epilogue: s1[r] = h[r]·a1s, d1[r] = h[r]·a1d (fp32, reduce 16 tx lanes)
    float4 as4 = *(const float4*)&a1s[tx * 4];
    float4 ad4 = *(const float4*)&a1d[tx * 4];
    #pragma unroll
    for (int i = 0; i < 4; i++) {
        float ps = acc[i][0] * as4.x + acc[i][1] * as4.y + acc[i][2] * as4.z + acc[i][3] * as4.w;
        float pd = acc[i][0] * ad4.x + acc[i][1] * ad4.y + acc[i][2] * ad4.z + acc[i][3] * ad4.w;
        #pragma unroll
        for (int o = 1; o < 16; o <<= 1) {
            ps += __shfl_xor_sync(~0u, ps, o);
            pd += __shfl_xor_sync(~0u, pd, o);
        }
        int gr = row0 + ty * 4 + i;
        if (tx == 0 && gr < NN) { g_s1[gr] = ps; g_d1[gr] = pd; }
    }
}

// ---------------- CSR construction ------------------------------------------
__global__ void k_zero_deg() {
    int i = blockIdx.x * blockDim.x + threadIdx.x;
    if (i < NN) g_deg[i] = 0;
}
__global__ void k_deg(const int* __restrict__ ei, int E) {
    int i = blockIdx.x * blockDim.x + threadIdx.x;
    if (i < E) {
        int d = ei[E + i];
        int p = 0;
        if (d >= 0 && d < NN) p = atomicAdd(&g_deg[d], 1);
        g_epos[i] = p;
    }
}
__global__ void k_scan1() {
    __shared__ int wsum[32];
    int i = blockIdx.x * 1024 + threadIdx.x;
    int t = threadIdx.x;
    int lane = t & 31, wid = t >> 5;
    int v = (i < NN) ? (g_deg[i] + 1) : 0;   // +1 = self loop
    int xval = v;
    #pragma unroll
    for (int o = 1; o < 32; o <<= 1) {
        int y = __shfl_up_sync(~0u, xval, o);
        if (lane >= o) xval += y;
    }
    if (lane == 31) wsum[wid] = xval;
    __syncthreads();
    if (wid == 0) {
        int w = wsum[lane];
        #pragma unroll
        for (int o = 1; o < 32; o <<= 1) {
            int y = __shfl_up_sync(~0u, w, o);
            if (lane >= o) w += y;
        }
        wsum[lane] = w;
    }
    __syncthreads();
    int incl = xval + (wid ? wsum[wid - 1] : 0);
    if (i < NN) g_rowptr[i] = incl - v;       // local exclusive
    if (t == 1023) g_bsum[blockIdx.x] = incl;
}
__global__ void k_scan2(int nb) {
    __shared__ int s[128];
    int t = threadIdx.x;
    int v = (t < nb) ? g_bsum[t] : 0;
    s[t] = v;
    __syncthreads();
    #pragma unroll
    for (int off = 1; off < 128; off <<= 1) {
        int y = (t >= off) ? s[t - off] : 0;
        __syncthreads();
        s[t] += y;
        __syncthreads();
    }
    if (t < nb) g_boff[t] = s[t] - v;   // exclusive
}
__global__ void k_scan3(int Etot) {
    int i = blockIdx.x * blockDim.x + threadIdx.x;
    if (i < NN) g_rowptr[i] += g_boff[i >> 10];
    if (i == 0) g_rowptr[NN] = Etot;
}
__global__ void k_scatter(const int* __restrict__ ei, int E) {
    int i = blockIdx.x * blockDim.x + threadIdx.x;
    if (i >= E + NN) return;
    int s, d, p;
    if (i < E) {
        s = ei[i];
        d = ei[E + i];
        if (d < 0 || d >= NN) return;
        p = g_rowptr[d] + g_epos[i];
    } else {
        d = s = i - E;
        p = g_rowptr[d] + g_deg[d];     // self loop occupies last slot
    }
    if (p >= 0 && p < ET_MAX) { g_esrc[p] = s; g_edst[p] = d; }
}

// ---------------- edge-parallel attention weights ----------------------------
__global__ void k_ew(int Etot) {
    int j = blockIdx.x * blockDim.x + threadIdx.x;
    if (j < Etot) {
        int u = g_esrc[j];
        int d = g_edst[j];
        float t = g_s1[u] + g_d1[d];
        t = t > 0.f ? t : 0.2f * t;
        g_ew[j] = __expf(t);
    }
}

// ------ layer-1 aggregation + fused layer-2 projection (warp per dst) -------
// shfl-free inner loop: uniform broadcast loads of esrc/ew + coalesced gather
__global__ void k_agg1(const float* __restrict__ b1, const float* __restrict__ W2,
                       const float* __restrict__ a2s, const float* __restrict__ a2d) {
    int v    = (blockIdx.x * blockDim.x + threadIdx.x) >> 5;
    int lane = threadIdx.x & 31;
    if (v >= NN) return;
    int beg = g_rowptr[v], end = g_rowptr[v + 1];
    const __half2* h1h = (const __half2*)g_h1f;

    float den = 0.f;
    float2 acc = make_float2(0.f, 0.f);
    #pragma unroll 8
    for (int j = beg; j < end; j++) {
        int   uu = g_esrc[j];               // uniform broadcast (L1-hit)
        float wt = g_ew[j];                 // uniform broadcast (L1-hit)
        den += wt;
        float2 f = __half22float2(h1h[uu * 32 + lane]);
        acc.x += wt * f.x;
        acc.y += wt * f.y;
    }
    float inv = 1.f / den;                  // den uniform across lanes
    float2 bb = *(const float2*)&b1[lane * 2];
    float rx = fmaxf(acc.x * inv + bb.x, 0.f);   // relu'd hr row, comps 2*lane, 2*lane+1
    float ry = fmaxf(acc.y * inv + bb.y, 0.f);

    // fused layer-2 projection: h2 = hr @ W2  (W2 is [64][2] row-major)
    float4 w4 = *(const float4*)&W2[lane * 4];
    float c0 = rx * w4.x + ry * w4.z;
    float c1 = rx * w4.y + ry * w4.w;
    #pragma unroll
    for (int o = 16; o; o >>= 1) {
        c0 += __shfl_xor_sync(~0u, c0, o);
        c1 += __shfl_xor_sync(~0u, c1, o);
    }
    if (!lane) {
        float s2v = c0 * a2s[0] + c1 * a2s[1];
        float d2v = c0 * a2d[0] + c1 * a2d[1];
        g_p2[v] = make_float4(c0, c1, s2v, d2v);
    }
}

// ---------------- layer-2 aggregation (warp per dst node) -------------------
__global__ void k_agg2(float* __restrict__ out, const float* __restrict__ b2) {
    int v    = (blockIdx.x * blockDim.x + threadIdx.x) >> 5;
    int lane = threadIdx.x & 31;
    if (v >= NN) return;
    int beg = g_rowptr[v], end = g_rowptr[v + 1];
    float dv = g_p2[v].w;

    float den = 0.f, ax = 0.f, ay = 0.f;
    #pragma unroll 4
    for (int j = beg + lane; j < end; j += 32) {
        int u = g_esrc[j];
        float4 p = g_p2[u];                 // (h2.x, h2.y, s2, d2) one sector
        float t = p.z + dv;
        t = t > 0.f ? t : 0.2f * t;
        float wt = __expf(t);
        den += wt;
        ax  += wt * p.x;
        ay  += wt * p.y;
    }
    #pragma unroll
    for (int o = 16; o; o >>= 1) {
        den += __shfl_xor_sync(~0u, den, o);
        ax  += __shfl_xor_sync(~0u, ax, o);
        ay  += __shfl_xor_sync(~0u, ay, o);
    }
    if (!lane) {
        float inv = 1.f / den;
        out[v * 2 + 0] = ax * inv + b2[0];
        out[v * 2 + 1] = ay * inv + b2[1];
    }
}

// ---------------- second output: edge_index passthrough as float ------------
__global__ void k_ecpy4(const int* __restrict__ ei, float* __restrict__ out, int n4) {
    int i = blockIdx.x * blockDim.x + threadIdx.x;
    if (i < n4) {
        int4 v = ((const int4*)ei)[i];
        float4 f = make_float4((float)v.x, (float)v.y, (float)v.z, (float)v.w);
        ((float4*)out)[i] = f;
    }
}
__global__ void k_ecpy_tail(const int* __restrict__ ei, float* __restrict__ out,
                            int start, int n) {
    int i = start + blockIdx.x * blockDim.x + threadIdx.x;
    if (i < n) out[i] = (float)ei[i];
}

// ---------------- launch -----------------------------------------------------
extern "C" void kernel_launch(void* const* d_in, const int* in_sizes, int n_in,
                              void* d_out, int out_size) {
    const float* x   = (const float*)d_in[0];
    const int*   ei  = (const int*)  d_in[1];
    const float* W1  = (const float*)d_in[2];
    const float* a1s = (const float*)d_in[3];
    const float* a1d = (const float*)d_in[4];
    const float* b1  = (const float*)d_in[5];
    const float* W2  = (const float*)d_in[6];
    const float* a2s = (const float*)d_in[7];
    const float* a2d = (const float*)d_in[8];
    const float* b2  = (const float*)d_in[9];
    float* out = (float*)d_out;

    int E = in_sizes[1] / 2;       // 1,600,000
    int Etot = E + NN;
    int nb = (NN + 1023) / 1024;   // 98 scan blocks

    cudaStream_t s2 = g_hx.s2;

    // fork: side stream joins capture via event on the main (default) stream
    cudaEventRecord(g_hx.evA, 0);
    cudaStreamWaitEvent(s2, g_hx.evA, 0);

    // main stream: GEMM (with fused s1/d1)
    k_gemm1<<<(NN + 63) / 64, 256>>>(x, W1, a1s, a1d);

    // side stream: CSR build (independent of GEMM)
    k_zero_deg<<<(NN + 255) / 256, 256, 0, s2>>>();
    k_deg<<<(E + 255) / 256, 256, 0, s2>>>(ei, E);
    k_scan1<<<nb, 1024, 0, s2>>>();
    k_scan2<<<1, 128, 0, s2>>>(nb);
    k_scan3<<<(NN + 255) / 256, 256, 0, s2>>>(Etot);
    k_scatter<<<(Etot + 255) / 256, 256, 0, s2>>>(ei, E);
    cudaEventRecord(g_hx.evB, s2);

    // side stream: independent edge_index copy (overlaps with ew/agg1/agg2)
    int extra = out_size - NN * 2;
    if (extra > 0) {
        int n = extra < 2 * E ? extra : 2 * E;
        int n4 = n / 4;
        if (n4 > 0)
            k_ecpy4<<<(n4 + 255) / 256, 256, 0, s2>>>(ei, out + NN * 2, n4);
        if (n - n4 * 4 > 0)
            k_ecpy_tail<<<1, 256, 0, s2>>>(ei, out + NN * 2, n4 * 4, n);
    }
    cudaEventRecord(g_hx.evC, s2);

    // main stream: wait for CSR, then edge weights, then aggregate
    cudaStreamWaitEvent(0, g_hx.evB, 0);
    k_ew<<<(Etot + 255) / 256, 256>>>(Etot);
    k_agg1<<<(NN * 32 + 255) / 256, 256>>>(b1, W2, a2s, a2d);
    k_agg2<<<(NN * 32 + 255) / 256, 256>>>(out, b2);

    // join: main stream waits for side-stream tail (required for capture)
    cudaStreamWaitEvent(0, g_hx.evC, 0);
}

// round 17
// speedup vs baseline: 1.6352x; 1.6352x over previous
#include <cuda_runtime.h>
#include <cuda_fp16.h>
#include <mma.h>

using namespace nvcuda;

#define NN   100000
#define EE_MAX 1600000
#define ET_MAX (NN + EE_MAX)
#define FIN  165
#define HID  64

#define GR   128     // rows per GEMM block
#define KC   32      // k-chunk
#define KPAD 192     // FIN padded to multiple of KC
#define XLD  40      // Xs leading dim (floats)
#define WLD  72      // Ws leading dim
#define HLD  68      // Hs leading dim

// ---------------- scratch (device globals; no allocation allowed) ------------
__device__ float4 g_h1f[NN * 8];        // layer-1 features fp16: 8 float4 = 32 half2 per row
__device__ float  g_s1[NN], g_d1[NN];
__device__ float4 g_p2[NN];             // packed (h2.x, h2.y, s2, d2)
__device__ int    g_deg[NN];
__device__ int    g_epos[EE_MAX];       // within-row position of each edge
__device__ int    g_rowptr[NN + 1];
__device__ int    g_esrc[ET_MAX];
__device__ int    g_bsum[128], g_boff[128];

// side stream + events for capture fork/join (host-side resources, module load)
struct HxStreams {
    cudaStream_t s2;
    cudaEvent_t evA, evB, evC;
    HxStreams() {
        cudaStreamCreateWithFlags(&s2, cudaStreamNonBlocking);
        cudaEventCreateWithFlags(&evA, cudaEventDisableTiming);
        cudaEventCreateWithFlags(&evB, cudaEventDisableTiming);
        cudaEventCreateWithFlags(&evC, cudaEventDisableTiming);
    }
};
static HxStreams g_hx;

// ------- GEMM1 (WMMA tf32): h1 = x @ W1, fused s1/d1 + fp16 pack epilogue ---
__global__ __launch_bounds__(256) void k_gemm1(
        const float* __restrict__ x, const float* __restrict__ W1,
        const float* __restrict__ a1s, const float* __restrict__ a1d) {
    // union region: tiles (Xs 128x40 + Ws 32x72 = 7424 floats) vs H (128x68 = 8704)
    __shared__ __align__(32) float smem[GR * HLD];
    __shared__ float As1[HID], Ad1[HID];
    float* Xs = smem;                 // [128][XLD]
    float* Ws = smem + GR * XLD;      // [32][WLD]
    float* Hs = smem;                 // [128][HLD] (after compute)

    const int tid  = threadIdx.x;     // 0..255
    const int warp = tid >> 5;        // 0..7, rows warp*16..+15
    const int row0 = blockIdx.x * GR;

    if (tid < HID)        As1[tid] = a1s[tid];
    else if (tid < 2*HID) Ad1[tid - HID] = a1d[tid - HID];

    wmma::fragment<wmma::matrix_a, 16, 16, 8, wmma::precision::tf32, wmma::row_major> af;
    wmma::fragment<wmma::matrix_b, 16, 16, 8, wmma::precision::tf32, wmma::row_major> bf;
    wmma::fragment<wmma::accumulator, 16, 16, 8, float> cf[4];
    #pragma unroll
    for (int c = 0; c < 4; c++) wmma::fill_fragment(cf[c], 0.f);

    for (int k0 = 0; k0 < KPAD; k0 += KC) {
        for (int i = tid; i < GR * KC; i += 256) {
            int r = i >> 5, k = i & 31;
            int gr = row0 + r, gk = k0 + k;
            Xs[r * XLD + k] = (gr < NN && gk < FIN) ? x[gr * FIN + gk] : 0.f;
        }
        for (int i = tid; i < KC * HID; i += 256) {
            int k = i >> 6, c = i & 63;
            int gk = k0 + k;
            Ws[k * WLD + c] = (gk < FIN) ? W1[gk * HID + c] : 0.f;
        }
        __syncthreads();
        #pragma unroll
        for (int ks = 0; ks < KC; ks += 8) {
            wmma::load_matrix_sync(af, &Xs[(warp * 16) * XLD + ks], XLD);
            #pragma unroll
            for (int i = 0; i < af.num_elements; i++)
                af.x[i] = wmma::__float_to_tf32(af.x[i]);
            #pragma unroll
            for (int c = 0; c < 4; c++) {
                wmma::load_matrix_sync(bf, &Ws[ks * WLD + c * 16], WLD);
                #pragma unroll
                for (int i = 0; i < bf.num_elements; i++)
                    bf.x[i] = wmma::__float_to_tf32(bf.x[i]);
                wmma::mma_sync(cf[c], af, bf, cf[c]);
            }
        }
        __syncthreads();
    }

    #pragma unroll
    for (int c = 0; c < 4; c++)
        wmma::store_matrix_sync(&Hs[(warp * 16) * HLD + c * 16], cf[c], HLD,
                                wmma::mem_row_major);
    __syncthreads();

    // epilogue: thread r owns row r (r < 128)
    if (tid < GR) {
        int gr = row0 + tid;
        if (gr < NN) {
            const float* hrow = &Hs[tid * HLD];
            float s = 0.f, d = 0.f;
            #pragma unroll
            for (int j = 0; j < HID; j++) {
                float h = hrow[j];
                s += h * As1[j];
                d += h * Ad1[j];
            }
            g_s1[gr] = s;
            g_d1[gr] = d;
            #pragma unroll
            for (int i = 0; i < 8; i++) {
                __half2 p0 = __floats2half2_rn(hrow[i*8+0], hrow[i*8+1]);
                __half2 p1 = __floats2half2_rn(hrow[i*8+2], hrow[i*8+3]);
                __half2 p2 = __floats2half2_rn(hrow[i*8+4], hrow[i*8+5]);
                __half2 p3 = __floats2half2_rn(hrow[i*8+6], hrow[i*8+7]);
                float4 v;
                v.x = __uint_as_float(*(unsigned*)&p0);
                v.y = __uint_as_float(*(unsigned*)&p1);
                v.z = __uint_as_float(*(unsigned*)&p2);
                v.w = __uint_as_float(*(unsigned*)&p3);
                g_h1f[gr * 8 + i] = v;
            }
        }
    }
}

// ---------------- CSR construction ------------------------------------------
__global__ void k_zero_deg() {
    int i = blockIdx.x * blockDim.x + threadIdx.x;
    if (i < NN) g_deg[i] = 0;
}
__global__ void k_deg(const int* __restrict__ ei, int E) {
    int i = blockIdx.x * blockDim.x + threadIdx.x;
    if (i < E) {
        int d = ei[E + i];
        int p = 0;
        if (d >= 0 && d < NN) p = atomicAdd(&g_deg[d], 1);
        g_epos[i] = p;
    }
}
__global__ void k_scan1() {
    __shared__ int wsum[32];
    int i = blockIdx.x * 1024 + threadIdx.x;
    int t = threadIdx.x;
    int lane = t & 31, wid = t >> 5;
    int v = (i < NN) ? (g_deg[i] + 1) : 0;   // +1 = self loop
    int xval = v;
    #pragma unroll
    for (int o = 1; o < 32; o <<= 1) {
        int y = __shfl_up_sync(~0u, xval, o);
        if (lane >= o) xval += y;
    }
    if (lane == 31) wsum[wid] = xval;
    __syncthreads();
    if (wid == 0) {
        int w = wsum[lane];
        #pragma unroll
        for (int o = 1; o < 32; o <<= 1) {
            int y = __shfl_up_sync(~0u, w, o);
            if (lane >= o) w += y;
        }
        wsum[lane] = w;
    }
    __syncthreads();
    int incl = xval + (wid ? wsum[wid - 1] : 0);
    if (i < NN) g_rowptr[i] = incl - v;       // local exclusive
    if (t == 1023) g_bsum[blockIdx.x] = incl;
}
__global__ void k_scan2(int nb) {
    __shared__ int s[128];
    int t = threadIdx.x;
    int v = (t < nb) ? g_bsum[t] : 0;
    s[t] = v;
    __syncthreads();
    #pragma unroll
    for (int off = 1; off < 128; off <<= 1) {
        int y = (t >= off) ? s[t - off] : 0;
        __syncthreads();
        s[t] += y;
        __syncthreads();
    }
    if (t < nb) g_boff[t] = s[t] - v;   // exclusive
}
__global__ void k_scan3(int Etot) {
    int i = blockIdx.x * blockDim.x + threadIdx.x;
    if (i < NN) g_rowptr[i] += g_boff[i >> 10];
    if (i == 0) g_rowptr[NN] = Etot;
}
__global__ void k_scatter(const int* __restrict__ ei, int E) {
    int i = blockIdx.x * blockDim.x + threadIdx.x;
    if (i >= E + NN) return;
    int s, p;
    if (i < E) {
        s = ei[i];
        int d = ei[E + i];
        if (d < 0 || d >= NN) return;
        p = g_rowptr[d] + g_epos[i];
    } else {
        int v = i - E;
        s = v;
        p = g_rowptr[v] + g_deg[v];     // self loop occupies last slot
    }
    if (p >= 0 && p < ET_MAX) g_esrc[p] = s;
}

// ------ layer-1 aggregation + fused layer-2 projection (warp per dst) -------
__global__ void k_agg1(const float* __restrict__ b1, const float* __restrict__ W2,
                       const float* __restrict__ a2s, const float* __restrict__ a2d) {
    int v    = (blockIdx.x * blockDim.x + threadIdx.x) >> 5;
    int lane = threadIdx.x & 31;
    if (v >= NN) return;
    int beg = g_rowptr[v], end = g_rowptr[v + 1];
    float dv = g_d1[v];
    const __half2* h1h = (const __half2*)g_h1f;

    float den = 0.f;
    float2 acc = make_float2(0.f, 0.f);
    for (int base = beg; base < end; base += 32) {
        int cnt = min(32, end - base);
        int u = 0; float ew = 0.f;
        if (base + lane < end) {
            u = g_esrc[base + lane];
            float t = g_s1[u] + dv;
            t = t > 0.f ? t : 0.2f * t;
            ew = __expf(t);
        }
        #pragma unroll 4
        for (int t = 0; t < cnt; t++) {
            int   uu = __shfl_sync(~0u, u, t);
            float wt = __shfl_sync(~0u, ew, t);
            den += wt;
            float2 f = __half22float2(h1h[uu * 32 + lane]);
            acc.x += wt * f.x;
            acc.y += wt * f.y;
        }
    }
    float inv = 1.f / den;
    float2 bb = *(const float2*)&b1[lane * 2];
    float rx = fmaxf(acc.x * inv + bb.x, 0.f);
    float ry = fmaxf(acc.y * inv + bb.y, 0.f);

    float4 w4 = *(const float4*)&W2[lane * 4];
    float c0 = rx * w4.x + ry * w4.z;
    float c1 = rx * w4.y + ry * w4.w;
    #pragma unroll
    for (int o = 16; o; o >>= 1) {
        c0 += __shfl_xor_sync(~0u, c0, o);
        c1 += __shfl_xor_sync(~0u, c1, o);
    }
    if (!lane) {
        float s2v = c0 * a2s[0] + c1 * a2s[1];
        float d2v = c0 * a2d[0] + c1 * a2d[1];
        g_p2[v] = make_float4(c0, c1, s2v, d2v);
    }
}

// ---------------- layer-2 aggregation (warp per dst node) -------------------
__global__ void k_agg2(float* __restrict__ out, const float* __restrict__ b2) {
    int v    = (blockIdx.x * blockDim.x + threadIdx.x) >> 5;
    int lane = threadIdx.x & 31;
    if (v >= NN) return;
    int beg = g_rowptr[v], end = g_rowptr[v + 1];
    float dv = g_p2[v].w;

    float den = 0.f, ax = 0.f, ay = 0.f;
    #pragma unroll 4
    for (int j = beg + lane; j < end; j += 32) {
        int u = g_esrc[j];
        float4 p = g_p2[u];
        float t = p.z + dv;
        t = t > 0.f ? t : 0.2f * t;
        float wt = __expf(t);
        den += wt;
        ax  += wt * p.x;
        ay  += wt * p.y;
    }
    #pragma unroll
    for (int o = 16; o; o >>= 1) {
        den += __shfl_xor_sync(~0u, den, o);
        ax  += __shfl_xor_sync(~0u, ax, o);
        ay  += __shfl_xor_sync(~0u, ay, o);
    }
    if (!lane) {
        float inv = 1.f / den;
        out[v * 2 + 0] = ax * inv + b2[0];
        out[v * 2 + 1] = ay * inv + b2[1];
    }
}

// ---------------- second output: edge_index passthrough as float ------------
__global__ void k_ecpy4(const int* __restrict__ ei, float* __restrict__ out, int n4) {
    int i = blockIdx.x * blockDim.x + threadIdx.x;
    if (i < n4) {
        int4 v = ((const int4*)ei)[i];
        float4 f = make_float4((float)v.x, (float)v.y, (float)v.z, (float)v.w);
        ((float4*)out)[i] = f;
    }
}
__global__ void k_ecpy_tail(const int* __restrict__ ei, float* __restrict__ out,
                            int start, int n) {
    int i = start + blockIdx.x * blockDim.x + threadIdx.x;
    if (i < n) out[i] = (float)ei[i];
}

// ---------------- launch -----------------------------------------------------
extern "C" void kernel_launch(void* const* d_in, const int* in_sizes, int n_in,
                              void* d_out, int out_size) {
    const float* x   = (const float*)d_in[0];
    const int*   ei  = (const int*)  d_in[1];
    const float* W1  = (const float*)d_in[2];
    const float* a1s = (const float*)d_in[3];
    const float* a1d = (const float*)d_in[4];
    const float* b1  = (const float*)d_in[5];
    const float* W2  = (const float*)d_in[6];
    const float* a2s = (const float*)d_in[7];
    const float* a2d = (const float*)d_in[8];
    const float* b2  = (const float*)d_in[9];
    float* out = (float*)d_out;

    int E = in_sizes[1] / 2;       // 1,600,000
    int Etot = E + NN;
    int nb = (NN + 1023) / 1024;   // 98 scan blocks

    cudaStream_t s2 = g_hx.s2;

    cudaEventRecord(g_hx.evA, 0);
    cudaStreamWaitEvent(s2, g_hx.evA, 0);

    // main stream: tf32 tensor-core GEMM (fused s1/d1 + fp16 pack)
    k_gemm1<<<(NN + GR - 1) / GR, 256>>>(x, W1, a1s, a1d);

    // side stream: CSR build
    k_zero_deg<<<(NN + 255) / 256, 256, 0, s2>>>();
    k_deg<<<(E + 255) / 256, 256, 0, s2>>>(ei, E);
    k_scan1<<<nb, 1024, 0, s2>>>();
    k_scan2<<<1, 128, 0, s2>>>(nb);
    k_scan3<<<(NN + 255) / 256, 256, 0, s2>>>(Etot);
    k_scatter<<<(Etot + 255) / 256, 256, 0, s2>>>(ei, E);
    cudaEventRecord(g_hx.evB, s2);

    // side stream: edge_index copy (overlaps agg1/agg2)
    int extra = out_size - NN * 2;
    if (extra > 0) {
        int n = extra < 2 * E ? extra : 2 * E;
        int n4 = n / 4;
        if (n4 > 0)
            k_ecpy4<<<(n4 + 255) / 256, 256, 0, s2>>>(ei, out + NN * 2, n4);
        if (n - n4 * 4 > 0)
            k_ecpy_tail<<<1, 256, 0, s2>>>(ei, out + NN * 2, n4 * 4, n);
    }
    cudaEventRecord(g_hx.evC, s2);

    cudaStreamWaitEvent(0, g_hx.evB, 0);
    k_agg1<<<(NN * 32 + 255) / 256, 256>>>(b1, W2, a2s, a2d);
    k_agg2<<<(NN * 32 + 255) / 256, 256>>>(out, b2);

    cudaStreamWaitEvent(0, g_hx.evC, 0);
}